// round 10
// baseline (speedup 1.0000x reference)
#include <cuda_runtime.h>
#include <cuda_bf16.h>
#include <cstdint>
#include <math.h>

#define TT 1024
#define BB 4
#define HH 1024
#define VV 32000
#define NBLK 128
#define UPB 8

typedef unsigned long long ull;

// ======================= helpers =======================
__device__ __forceinline__ uint32_t smem_to_u32(const void* p) {
    uint32_t a;
    asm("{ .reg .u64 t; cvta.to.shared.u64 t, %1; cvt.u32.u64 %0, t; }" : "=r"(a) : "l"(p));
    return a;
}
__device__ __forceinline__ void cp16(uint32_t dst, const void* src) {
    asm volatile("cp.async.cg.shared.global [%0], [%1], 16;" :: "r"(dst), "l"(src) : "memory");
}
#define CP_COMMIT() asm volatile("cp.async.commit_group;" ::: "memory")
#define CP_WAIT(n)  asm volatile("cp.async.wait_group %0;" :: "n"(n) : "memory")

#define LDSM_X4(r0, r1, r2, r3, addr) \
    asm volatile("ldmatrix.sync.aligned.m8n8.x4.shared.b16 {%0,%1,%2,%3}, [%4];" \
        : "=r"(r0), "=r"(r1), "=r"(r2), "=r"(r3) : "r"(addr))
#define MMA16816(c0, c1, c2, c3, a0, a1, a2, a3, b0, b1) \
    asm volatile("mma.sync.aligned.m16n8k16.row.col.f32.bf16.bf16.f32 " \
        "{%0,%1,%2,%3}, {%4,%5,%6,%7}, {%8,%9}, {%0,%1,%2,%3};" \
        : "+f"(c0), "+f"(c1), "+f"(c2), "+f"(c3) \
        : "r"(a0), "r"(a1), "r"(a2), "r"(a3), "r"(b0), "r"(b1))

// packed dual-fp32 FMA (FFMA2): acc.xy += w.xy * h.xy
#define FMA2(acc, w, h) \
    asm("fma.rn.f32x2 %0, %1, %2, %0;" : "+l"(acc) : "l"(w), "l"(h))
__device__ __forceinline__ float f2sum(ull v) {
    return __uint_as_float((unsigned)v) + __uint_as_float((unsigned)(v >> 32));
}

// ======================= scratch =======================
__device__ __nv_bfloat16 g_weh[(size_t)VV * HH];
__device__ __nv_bfloat16 g_wel[(size_t)VV * HH];
__device__ __nv_bfloat16 g_wihh[(size_t)2 * 4 * HH * HH];
__device__ __nv_bfloat16 g_wihl[(size_t)2 * 4 * HH * HH];
__device__ __nv_bfloat16 g_fh[(size_t)TT * BB * HH];
__device__ __nv_bfloat16 g_fl[(size_t)TT * BB * HH];
__device__ __nv_bfloat16 g_h0h[(size_t)TT * BB * HH];
__device__ __nv_bfloat16 g_h0l[(size_t)TT * BB * HH];
__device__ __nv_bfloat16 g_xnh[(size_t)TT * BB * HH];
__device__ __nv_bfloat16 g_xnl[(size_t)TT * BB * HH];
__device__ float g_gates[(size_t)TT * BB * 4 * HH];
__device__ float g_h0[(size_t)TT * BB * HH];
__device__ float g_h1[(size_t)TT * BB * HH];
__device__ unsigned g_counter;

__device__ __forceinline__ void split_bf16(float v, __nv_bfloat16& hi, __nv_bfloat16& lo) {
    __nv_bfloat16 h = __float2bfloat16(v);
    hi = h;
    lo = __float2bfloat16(v - __bfloat162float(h));
}

// ======================= fp32 -> bf16 hi/lo split =======================
__global__ __launch_bounds__(256) void convsplit_kernel(
    const float* __restrict__ in, __nv_bfloat16* __restrict__ hi,
    __nv_bfloat16* __restrict__ lo, int n4)
{
    int i = blockIdx.x * blockDim.x + threadIdx.x;
    if (i >= n4) return;
    float4 v = ((const float4*)in)[i];
    __nv_bfloat16 h0, h1, h2, h3, l0, l1, l2, l3;
    split_bf16(v.x, h0, l0); split_bf16(v.y, h1, l1);
    split_bf16(v.z, h2, l2); split_bf16(v.w, h3, l3);
    ((__nv_bfloat162*)hi)[i * 2 + 0] = __nv_bfloat162(h0, h1);
    ((__nv_bfloat162*)hi)[i * 2 + 1] = __nv_bfloat162(h2, h3);
    ((__nv_bfloat162*)lo)[i * 2 + 0] = __nv_bfloat162(l0, l1);
    ((__nv_bfloat162*)lo)[i * 2 + 1] = __nv_bfloat162(l2, l3);
}

// ======================= embedding -> bf16 split, time-major =======================
__global__ __launch_bounds__(256) void embed_kernel(
    const int* __restrict__ ids, const float* __restrict__ we,
    const float* __restrict__ pe, __nv_bfloat16* __restrict__ oh,
    __nv_bfloat16* __restrict__ ol)
{
    int t = blockIdx.x, b = blockIdx.y;
    int id = ids[b * TT + t];
    const float4* w = (const float4*)(we + (size_t)id * HH);
    const float4* p = (const float4*)(pe + (size_t)t * HH);
    size_t row = ((size_t)t * BB + b) * HH;
    for (int i = threadIdx.x; i < HH / 4; i += blockDim.x) {
        float4 a = w[i], c = p[i];
        float4 v = make_float4(a.x + c.x, a.y + c.y, a.z + c.z, a.w + c.w);
        __nv_bfloat16 h0, h1, h2, h3, l0, l1, l2, l3;
        split_bf16(v.x, h0, l0); split_bf16(v.y, h1, l1);
        split_bf16(v.z, h2, l2); split_bf16(v.w, h3, l3);
        ((__nv_bfloat162*)(oh + row))[i * 2 + 0] = __nv_bfloat162(h0, h1);
        ((__nv_bfloat162*)(oh + row))[i * 2 + 1] = __nv_bfloat162(h2, h3);
        ((__nv_bfloat162*)(ol + row))[i * 2 + 0] = __nv_bfloat162(l0, l1);
        ((__nv_bfloat162*)(ol + row))[i * 2 + 1] = __nv_bfloat162(l2, l3);
    }
}

// ======================= HMMA split-bf16 NT GEMM (known-good, unchanged) =======================
#define TSTRIDE 40
#define TILE_E  (128 * TSTRIDE)
#define TILE_BYTES (TILE_E * 2)            // 10240
#define BUF_BYTES (4 * TILE_BYTES)         // 40960
#define GSMEM (2 * BUF_BYTES)              // 81920

__global__ __launch_bounds__(256, 2) void gemm_hmma_kernel(
    const __nv_bfloat16* __restrict__ Ah, const __nv_bfloat16* __restrict__ Al,
    const __nv_bfloat16* __restrict__ Bh, const __nv_bfloat16* __restrict__ Bl,
    const float* __restrict__ bias0, const float* __restrict__ bias1,
    float* __restrict__ C, int N)
{
    extern __shared__ __nv_bfloat16 sm[];
    const uint32_t sbase = smem_to_u32(sm);
    const int tid = threadIdx.x;
    const int lane = tid & 31;
    const int wid = tid >> 5;
    const int wm = wid & 3;
    const int wn = wid >> 2;
    const int bn = blockIdx.x << 7;
    const int bm = blockIdx.y << 7;

    float acc[2][8][4];
#pragma unroll
    for (int mt = 0; mt < 2; ++mt)
#pragma unroll
        for (int nt = 0; nt < 8; ++nt)
#pragma unroll
            for (int q = 0; q < 4; ++q) acc[mt][nt][q] = 0.f;

    const __nv_bfloat16* srcs[4] = { Ah, Al, Bh, Bl };
    const int rb[4] = { bm, bm, bn, bn };

    auto load_chunk = [&](int c) {
        uint32_t buf = sbase + (c & 1) * BUF_BYTES;
#pragma unroll
        for (int tsel = 0; tsel < 4; ++tsel) {
            uint32_t dst = buf + tsel * TILE_BYTES;
            const __nv_bfloat16* base = srcs[tsel];
#pragma unroll
            for (int i = 0; i < 2; ++i) {
                int s = tid + (i << 8);
                int row = s >> 2, k8 = s & 3;
                cp16(dst + row * (TSTRIDE * 2) + k8 * 16,
                     base + (size_t)(rb[tsel] + row) * 1024 + c * 32 + k8 * 8);
            }
        }
        CP_COMMIT();
    };

    load_chunk(0);

    for (int c = 0; c < 32; ++c) {
        if (c < 31) { load_chunk(c + 1); CP_WAIT(1); }
        else        { CP_WAIT(0); }
        __syncthreads();

        uint32_t buf = sbase + (c & 1) * BUF_BYTES;
        const int a_r = (lane & 15);
        const int a_k = (lane >> 4) << 3;
        const int b_n = ((lane >> 4) << 3) + (lane & 7);
        const int b_k = ((lane >> 3) & 1) << 3;

#pragma unroll
        for (int ks = 0; ks < 2; ++ks) {
            const int kbase = ks << 4;
            uint32_t ah[2][4], al[2][4], bh[16], bl[16];
#pragma unroll
            for (int mt = 0; mt < 2; ++mt) {
                int row = wm * 32 + mt * 16 + a_r;
                uint32_t addr = buf + (row * TSTRIDE + kbase + a_k) * 2;
                LDSM_X4(ah[mt][0], ah[mt][1], ah[mt][2], ah[mt][3], addr);
                LDSM_X4(al[mt][0], al[mt][1], al[mt][2], al[mt][3], addr + TILE_BYTES);
            }
#pragma unroll
            for (int np = 0; np < 4; ++np) {
                int nrow = wn * 64 + np * 16 + b_n;
                uint32_t addr = buf + 2 * TILE_BYTES + (nrow * TSTRIDE + kbase + b_k) * 2;
                LDSM_X4(bh[np * 4 + 0], bh[np * 4 + 1], bh[np * 4 + 2], bh[np * 4 + 3], addr);
                LDSM_X4(bl[np * 4 + 0], bl[np * 4 + 1], bl[np * 4 + 2], bl[np * 4 + 3],
                        addr + TILE_BYTES);
            }
#pragma unroll
            for (int mt = 0; mt < 2; ++mt)
#pragma unroll
                for (int nt = 0; nt < 8; ++nt) {
                    float* cc = acc[mt][nt];
                    MMA16816(cc[0], cc[1], cc[2], cc[3],
                             ah[mt][0], ah[mt][1], ah[mt][2], ah[mt][3],
                             bh[nt * 2], bh[nt * 2 + 1]);
                    MMA16816(cc[0], cc[1], cc[2], cc[3],
                             al[mt][0], al[mt][1], al[mt][2], al[mt][3],
                             bh[nt * 2], bh[nt * 2 + 1]);
                    MMA16816(cc[0], cc[1], cc[2], cc[3],
                             ah[mt][0], ah[mt][1], ah[mt][2], ah[mt][3],
                             bl[nt * 2], bl[nt * 2 + 1]);
                }
        }
        __syncthreads();
    }

#pragma unroll
    for (int mt = 0; mt < 2; ++mt) {
        int row0 = bm + wm * 32 + mt * 16 + (lane >> 2);
#pragma unroll
        for (int nt = 0; nt < 8; ++nt) {
            int col = bn + wn * 64 + nt * 8 + ((lane & 3) << 1);
            float b0v = 0.f, b1v = 0.f;
            if (bias0) {
                b0v = bias0[col] + bias1[col];
                b1v = bias0[col + 1] + bias1[col + 1];
            }
            float* c0 = C + (size_t)row0 * N + col;
            float* c1 = C + (size_t)(row0 + 8) * N + col;
            *(float2*)c0 = make_float2(acc[mt][nt][0] + b0v, acc[mt][nt][1] + b1v);
            *(float2*)c1 = make_float2(acc[mt][nt][2] + b0v, acc[mt][nt][3] + b1v);
        }
    }
}

// ======================= persistent LSTM recurrence (warp-per-unit rewrite) =======================
// Warp w of block blk owns hidden unit u = blk*8+w: computes all 4 gates x 4 batches
// via lane-sliced dots + shfl butterfly. No part[]/gsm[] SMEM round-trips; cell state
// in registers (lanes 0-3). 3 syncthreads/step. Counter barrier as in R8.
__device__ __forceinline__ float sigm(float x) { return 1.f / (1.f + expf(-x)); }

__global__ __launch_bounds__(256) void lstm_layer_kernel(
    const float* __restrict__ gates_in, const float* __restrict__ Whh,
    float* __restrict__ hout, unsigned* counter)
{
    extern __shared__ float smf[];
    float* Wsh = smf;              // [8 warps][4 gates][1024] = 32 rows x 1024
    float* hsh = Wsh + 32 * 1024;  // [4][1024]

    const int tid = threadIdx.x;
    const int lane = tid & 31;
    const int w = tid >> 5;
    const int blk = blockIdx.x;
    const int u0 = blk * UPB;
    const int u = u0 + w;

    // load W shard: Wsh row (w*4+g) = Whh[g*HH + u0 + w][:]
#pragma unroll
    for (int r = 0; r < 32; ++r) {
        int wq = r >> 2, g = r & 3;
        *(float4*)(Wsh + r * 1024 + tid * 4) =
            *(const float4*)(Whh + (size_t)(g * HH + u0 + wq) * HH + tid * 4);
    }
    // zero h(-1)
#pragma unroll
    for (int q = 0; q < 4; ++q)
        ((float4*)hsh)[tid + 256 * q] = make_float4(0.f, 0.f, 0.f, 0.f);
    __syncthreads();

    const float* Wb = Wsh + (w * 4) * 1024;
    float cstate = 0.f;                 // lanes 0-3: cell state for batch=lane

    for (int t = 0; t < TT; ++t) {
        // prefetch gate inputs: lane (g*4+b) holds gates_in[t][b][g*HH+u]
        float gin = 0.f;
        if (lane < 16)
            gin = __ldg(gates_in + ((size_t)t * BB + (lane & 3)) * (4 * HH)
                        + (lane >> 2) * HH + u);

        if (t > 0) {
            if (tid == 0) {
                unsigned tgt = (unsigned)NBLK * (unsigned)t;
                unsigned v;
                do {
                    asm volatile("ld.acquire.gpu.global.u32 %0, [%1];"
                                 : "=r"(v) : "l"(counter));
                } while (v < tgt);
            }
            __syncthreads();
            const float4* hp = (const float4*)(hout + (size_t)(t - 1) * BB * HH);
#pragma unroll
            for (int q = 0; q < 4; ++q)
                ((float4*)hsh)[tid + 256 * q] = __ldcg(hp + tid + 256 * q);
            __syncthreads();
        }

        // 16 partial dots per lane over its k-slice (words 4*lane + 128*i)
        ull acc[4][4];
#pragma unroll
        for (int g = 0; g < 4; ++g)
#pragma unroll
            for (int b = 0; b < 4; ++b) acc[g][b] = 0ull;
#pragma unroll
        for (int i = 0; i < 8; ++i) {
            int off = 4 * lane + 128 * i;
            ulonglong2 hv0 = *(const ulonglong2*)(hsh + off);
            ulonglong2 hv1 = *(const ulonglong2*)(hsh + 1024 + off);
            ulonglong2 hv2 = *(const ulonglong2*)(hsh + 2048 + off);
            ulonglong2 hv3 = *(const ulonglong2*)(hsh + 3072 + off);
#pragma unroll
            for (int g = 0; g < 4; ++g) {
                ulonglong2 wv = *(const ulonglong2*)(Wb + g * 1024 + off);
                FMA2(acc[g][0], wv.x, hv0.x); FMA2(acc[g][0], wv.y, hv0.y);
                FMA2(acc[g][1], wv.x, hv1.x); FMA2(acc[g][1], wv.y, hv1.y);
                FMA2(acc[g][2], wv.x, hv2.x); FMA2(acc[g][2], wv.y, hv2.y);
                FMA2(acc[g][3], wv.x, hv3.x); FMA2(acc[g][3], wv.y, hv3.y);
            }
        }
        float s[16];
#pragma unroll
        for (int g = 0; g < 4; ++g)
#pragma unroll
            for (int b = 0; b < 4; ++b) s[g * 4 + b] = f2sum(acc[g][b]);
        // butterfly all-reduce across lanes
#pragma unroll
        for (int off = 16; off >= 1; off >>= 1)
#pragma unroll
            for (int q = 0; q < 16; ++q)
                s[q] += __shfl_xor_sync(0xffffffffu, s[q], off);
        // gather gate inputs to lanes 0-3 (b = lane)
        float gi4[4];
#pragma unroll
        for (int g = 0; g < 4; ++g)
            gi4[g] = __shfl_sync(0xffffffffu, gin, (g << 2) | (lane & 3));

        if (lane < 4) {
            int b = lane;
            float gI = s[0 * 4 + b] + gi4[0];
            float gF = s[1 * 4 + b] + gi4[1];
            float gG = s[2 * 4 + b] + gi4[2];
            float gO = s[3 * 4 + b] + gi4[3];
            float cn = sigm(gF) * cstate + sigm(gI) * tanhf(gG);
            float hn = sigm(gO) * tanhf(cn);
            cstate = cn;
            hout[((size_t)t * BB + b) * HH + u] = hn;
        }
        __syncthreads();   // all warps' h-stores precede tid0's release
        if (tid == 0) {
            asm volatile("red.release.gpu.global.add.u32 [%0], %1;"
                         :: "l"(counter), "r"(1u) : "memory");
        }
    }
}

__global__ void reset_counter_kernel(unsigned* c)
{
    if (threadIdx.x == 0) *c = 0u;
}

// ======================= LayerNorm -> bf16 split, batch-major =======================
__global__ __launch_bounds__(256) void layernorm_kernel(
    const float* __restrict__ in, const float* __restrict__ w,
    const float* __restrict__ bv, __nv_bfloat16* __restrict__ oh,
    __nv_bfloat16* __restrict__ ol)
{
    int t = blockIdx.x, b = blockIdx.y;
    const float* x = in + ((size_t)t * BB + b) * HH;
    size_t orow = ((size_t)b * TT + t) * HH;
    __shared__ float row[HH];
    __shared__ float red[8];
    __shared__ float stat[2];
    int tid = threadIdx.x;

    float s = 0.f;
    for (int i = tid; i < HH; i += 256) { float v = x[i]; row[i] = v; s += v; }
#pragma unroll
    for (int off = 16; off; off >>= 1) s += __shfl_xor_sync(0xffffffffu, s, off);
    if ((tid & 31) == 0) red[tid >> 5] = s;
    __syncthreads();
    if (tid == 0) {
        float tot = 0.f;
        for (int i = 0; i < 8; ++i) tot += red[i];
        stat[0] = tot * (1.f / HH);
    }
    __syncthreads();
    float mu = stat[0];
    float v2 = 0.f;
    for (int i = tid; i < HH; i += 256) { float d = row[i] - mu; v2 += d * d; }
#pragma unroll
    for (int off = 16; off; off >>= 1) v2 += __shfl_xor_sync(0xffffffffu, v2, off);
    __syncthreads();
    if ((tid & 31) == 0) red[tid >> 5] = v2;
    __syncthreads();
    if (tid == 0) {
        float tot = 0.f;
        for (int i = 0; i < 8; ++i) tot += red[i];
        stat[1] = rsqrtf(tot * (1.f / HH) + 1e-5f);
    }
    __syncthreads();
    float inv = stat[1];
    for (int i = tid; i < HH; i += 256) {
        float v = (row[i] - mu) * inv * w[i] + bv[i];
        __nv_bfloat16 hi, lo;
        split_bf16(v, hi, lo);
        oh[orow + i] = hi;
        ol[orow + i] = lo;
    }
}

// ======================= launch =======================
extern "C" void kernel_launch(void* const* d_in, const int* in_sizes, int n_in,
                              void* d_out, int out_size)
{
    (void)in_sizes; (void)n_in; (void)out_size;
    const int*   ids = (const int*)d_in[0];
    const float* we  = (const float*)d_in[1];
    const float* pe  = (const float*)d_in[2];
    const float* Wih = (const float*)d_in[3];
    const float* Whh = (const float*)d_in[4];
    const float* bih = (const float*)d_in[5];
    const float* bhh = (const float*)d_in[6];
    const float* lnw = (const float*)d_in[7];
    const float* lnb = (const float*)d_in[8];
    float* out = (float*)d_out;

    __nv_bfloat16 *weh, *wel, *wihh, *wihl, *fh, *fl, *h0h, *h0l, *xnh, *xnl;
    float *gates, *h0, *h1; unsigned* counter;
    cudaGetSymbolAddress((void**)&weh,  g_weh);
    cudaGetSymbolAddress((void**)&wel,  g_wel);
    cudaGetSymbolAddress((void**)&wihh, g_wihh);
    cudaGetSymbolAddress((void**)&wihl, g_wihl);
    cudaGetSymbolAddress((void**)&fh,   g_fh);
    cudaGetSymbolAddress((void**)&fl,   g_fl);
    cudaGetSymbolAddress((void**)&h0h,  g_h0h);
    cudaGetSymbolAddress((void**)&h0l,  g_h0l);
    cudaGetSymbolAddress((void**)&xnh,  g_xnh);
    cudaGetSymbolAddress((void**)&xnl,  g_xnl);
    cudaGetSymbolAddress((void**)&gates, g_gates);
    cudaGetSymbolAddress((void**)&h0,    g_h0);
    cudaGetSymbolAddress((void**)&h1,    g_h1);
    cudaGetSymbolAddress((void**)&counter, g_counter);

    size_t lsmem = (size_t)(32 * 1024 + 4 * 1024) * sizeof(float);   // 147456
    cudaFuncSetAttribute(lstm_layer_kernel,
                         cudaFuncAttributeMaxDynamicSharedMemorySize, (int)lsmem);
    cudaFuncSetAttribute(gemm_hmma_kernel,
                         cudaFuncAttributeMaxDynamicSharedMemorySize, GSMEM);

    // weight/input splits
    convsplit_kernel<<<(VV * HH / 4 + 255) / 256, 256>>>(we, weh, wel, VV * HH / 4);
    convsplit_kernel<<<(2 * 4 * HH * HH / 4 + 255) / 256, 256>>>(Wih, wihh, wihl,
                                                                 2 * 4 * HH * HH / 4);
    embed_kernel<<<dim3(TT, BB), 256>>>(ids, we, pe, fh, fl);

    // layer0 input gates
    gemm_hmma_kernel<<<dim3(4 * HH / 128, TT * BB / 128), 256, GSMEM>>>(
        fh, fl, wihh, wihl, bih, bhh, gates, 4 * HH);
    reset_counter_kernel<<<1, 32>>>(counter);
    lstm_layer_kernel<<<NBLK, 256, lsmem>>>(gates, Whh, h0, counter);

    // layer1
    convsplit_kernel<<<(TT * BB * HH / 4 + 255) / 256, 256>>>(h0, h0h, h0l, TT * BB * HH / 4);
    gemm_hmma_kernel<<<dim3(4 * HH / 128, TT * BB / 128), 256, GSMEM>>>(
        h0h, h0l, wihh + (size_t)4 * HH * HH, wihl + (size_t)4 * HH * HH,
        bih + 4 * HH, bhh + 4 * HH, gates, 4 * HH);
    reset_counter_kernel<<<1, 32>>>(counter);
    lstm_layer_kernel<<<NBLK, 256, lsmem>>>(gates, Whh + (size_t)4 * HH * HH, h1, counter);

    // layernorm + head
    layernorm_kernel<<<dim3(TT, BB), 256>>>(h1, lnw, lnb, xnh, xnl);
    gemm_hmma_kernel<<<dim3(VV / 128, TT * BB / 128), 256, GSMEM>>>(
        xnh, xnl, weh, wel, nullptr, nullptr, out, VV);
}